// round 2
// baseline (speedup 1.0000x reference)
#include <cuda_runtime.h>
#include <cstdint>

// ============================================================================
// Problem constants
// ============================================================================
#define D_DIM 4096
#define BM 128
#define BN 128
#define BK 64                   // bytes of K per pipeline stage
#define NSTAGE 4
#define KT_ITERS (D_DIM / BK)   // 64
#define THREADS 256

// ============================================================================
// Scratch (device globals; no allocation allowed)
// ============================================================================
__device__ __align__(1024) signed char g_qx[(size_t)D_DIM * D_DIM]; // int8 activations
__device__ __align__(1024) signed char g_wq[(size_t)D_DIM * D_DIM]; // int8 weights
__device__ float g_sx[D_DIM];                                        // activation row scales

// ============================================================================
// PTX helpers — base ISA only (sm_80+): cp.async, ldmatrix, mma.sync IMMA
// ============================================================================
__device__ __forceinline__ uint32_t smem_u32(const void* p) {
    uint32_t a;
    asm("{ .reg .u64 t; cvta.to.shared.u64 t, %1; cvt.u32.u64 %0, t; }" : "=r"(a) : "l"(p));
    return a;
}

#define CP_ASYNC16(dst, src) \
    asm volatile("cp.async.cg.shared.global [%0], [%1], 16;" :: "r"(dst), "l"(src))
#define CP_COMMIT() asm volatile("cp.async.commit_group;" ::: "memory")
#define CP_WAIT2()  asm volatile("cp.async.wait_group 2;" ::: "memory")

#define LDM_X4(r, addr) \
    asm volatile("ldmatrix.sync.aligned.m8n8.x4.shared.b16 {%0,%1,%2,%3}, [%4];" \
                 : "=r"((r)[0]), "=r"((r)[1]), "=r"((r)[2]), "=r"((r)[3]) : "r"(addr))

#define MMA_S8(c, a, b0, b1) \
    asm volatile("mma.sync.aligned.m16n8k32.row.col.s32.s8.s8.s32 " \
                 "{%0,%1,%2,%3},{%4,%5,%6,%7},{%8,%9},{%0,%1,%2,%3};" \
                 : "+r"((c)[0]), "+r"((c)[1]), "+r"((c)[2]), "+r"((c)[3]) \
                 : "r"((a)[0]), "r"((a)[1]), "r"((a)[2]), "r"((a)[3]), "r"(b0), "r"(b1))

// SMEM tile layout: 128 rows x 64 bytes/row, 16B chunks swizzled:
//   phys_chunk = chunk ^ ((row >> 1) & 3)
// -> conflict-free for both cp.async 16B stores and ldmatrix reads.
__device__ __forceinline__ uint32_t tile_off(int row, int chunk) {
    return (uint32_t)(row * 64 + ((chunk ^ ((row >> 1) & 3)) << 4));
}

// ============================================================================
// Kernel 1: weight int32 -> int8
// ============================================================================
__global__ void wconv_kernel(const int4* __restrict__ w, char4* __restrict__ o, int n4) {
    int i = blockIdx.x * blockDim.x + threadIdx.x;
    if (i < n4) {
        int4 v = w[i];
        char4 u;
        u.x = (signed char)v.x;
        u.y = (signed char)v.y;
        u.z = (signed char)v.z;
        u.w = (signed char)v.w;
        o[i] = u;
    }
}

// ============================================================================
// Kernel 2: blockwise-256 Hadamard (FWHT) + per-row int4 quantize -> int8
// One CTA (512 threads = 16 warps) per row; warp w handles 256-elem segment w.
// ============================================================================
__global__ __launch_bounds__(512) void hadq_kernel(
    const float* __restrict__ x, signed char* __restrict__ qx, float* __restrict__ sxv)
{
    __shared__ float smax[16];
    int row  = blockIdx.x;
    int w    = threadIdx.x >> 5;
    int lane = threadIdx.x & 31;

    const float* xr = x + (size_t)row * D_DIM + w * 256;
    float v[8];
#pragma unroll
    for (int j = 0; j < 8; j++) v[j] = xr[j * 32 + lane];

    // local butterflies: strides 32,64,128 (bits of the per-lane index j)
#pragma unroll
    for (int b = 1; b < 8; b <<= 1) {
#pragma unroll
        for (int j = 0; j < 8; j++) {
            if (!(j & b)) {
                float a = v[j], c = v[j | b];
                v[j]     = a + c;
                v[j | b] = a - c;
            }
        }
    }
    // lane butterflies: strides 1..16
#pragma unroll
    for (int s = 1; s < 32; s <<= 1) {
#pragma unroll
        for (int j = 0; j < 8; j++) {
            float o = __shfl_xor_sync(0xFFFFFFFFu, v[j], s);
            v[j] = (lane & s) ? (o - v[j]) : (v[j] + o);
        }
    }
#pragma unroll
    for (int j = 0; j < 8; j++) v[j] *= 0.0625f;   // 1/sqrt(256)

    float mx = 0.0f;
#pragma unroll
    for (int j = 0; j < 8; j++) mx = fmaxf(mx, fabsf(v[j]));
#pragma unroll
    for (int s = 16; s; s >>= 1) mx = fmaxf(mx, __shfl_xor_sync(0xFFFFFFFFu, mx, s));
    if (lane == 0) smax[w] = mx;
    __syncthreads();
    float tot = smax[0];
#pragma unroll
    for (int i = 1; i < 16; i++) tot = fmaxf(tot, smax[i]);

    if (threadIdx.x == 0) sxv[row] = tot * (1.0f / 7.0f);
    float inv = 7.0f / tot;

    signed char* qr = qx + (size_t)row * D_DIM + w * 256;
#pragma unroll
    for (int j = 0; j < 8; j++) {
        float q = rintf(v[j] * inv);               // round-half-even == jnp.round
        q = fminf(fmaxf(q, -8.0f), 7.0f);
        qr[j * 32 + lane] = (signed char)(int)q;
    }
}

// ============================================================================
// Kernel 3: int8 GEMM (mma.sync IMMA) + fused dequant epilogue
// CTA tile 128x128, 4-stage cp.async pipeline, 8 warps each 64x32.
// out[m][n] = acc[m][n] * sx[m] * ws[n] + bias[n]
// ============================================================================
__global__ __launch_bounds__(THREADS) void gemm_kernel(
    const signed char* __restrict__ gA,   // [4096,4096] int8 (m,k)
    const signed char* __restrict__ gB,   // [4096,4096] int8 (n,k)
    const float* __restrict__ sx,
    const float* __restrict__ ws,
    const float* __restrict__ bias,
    float* __restrict__ out)
{
    extern __shared__ char smem[];
    uint32_t sbase = smem_u32(smem);
    const uint32_t sA0 = sbase;                  // NSTAGE x 8192
    const uint32_t sB0 = sbase + NSTAGE * 8192;  // NSTAGE x 8192

    int tid  = threadIdx.x;
    int lane = tid & 31;
    int wid  = tid >> 5;
    int m0 = blockIdx.x * BM;
    int n0 = blockIdx.y * BN;
    int wm = wid & 1;          // 2 warps over M
    int wn = wid >> 1;         // 4 warps over N
    int Amb = wm * 64;         // warp M base within tile
    int Bnb = wn * 32;         // warp N base within tile
    int i8 = lane & 7, g = lane >> 3;

    int acc[4][4][4];
#pragma unroll
    for (int a = 0; a < 4; a++)
#pragma unroll
        for (int b = 0; b < 4; b++)
#pragma unroll
            for (int c = 0; c < 4; c++) acc[a][b][c] = 0;

    // loader lambda (2 chunks of A + 2 chunks of B per thread per stage)
    auto load_stage = [&](int kt, int buf) {
        int kb = kt * BK;
        uint32_t dA = sA0 + buf * 8192;
        uint32_t dB = sB0 + buf * 8192;
#pragma unroll
        for (int r = 0; r < 2; r++) {
            int ci  = tid + r * 256;
            int row = ci >> 2, ch = ci & 3;
            CP_ASYNC16(dA + tile_off(row, ch),
                       gA + (size_t)(m0 + row) * D_DIM + kb + ch * 16);
        }
#pragma unroll
        for (int r = 0; r < 2; r++) {
            int ci  = tid + r * 256;
            int row = ci >> 2, ch = ci & 3;
            CP_ASYNC16(dB + tile_off(row, ch),
                       gB + (size_t)(n0 + row) * D_DIM + kb + ch * 16);
        }
    };

    // prologue: fill 3 stages
#pragma unroll
    for (int s = 0; s < NSTAGE - 1; s++) {
        load_stage(s, s);
        CP_COMMIT();
    }

    for (int kt = 0; kt < KT_ITERS; kt++) {
        CP_WAIT2();            // stage kt resident
        __syncthreads();       // visible to all warps; prev-iter compute done

        int ldkt = kt + NSTAGE - 1;
        if (ldkt < KT_ITERS) load_stage(ldkt, ldkt & (NSTAGE - 1));
        CP_COMMIT();           // empty groups at tail keep the count consistent

        uint32_t sA = sA0 + (kt & (NSTAGE - 1)) * 8192;
        uint32_t sB = sB0 + (kt & (NSTAGE - 1)) * 8192;

#pragma unroll
        for (int ks = 0; ks < 2; ks++) {           // two k32 steps per stage
            uint32_t a[4][4], b[2][4];
#pragma unroll
            for (int mb = 0; mb < 4; mb++) {
                int row = Amb + mb * 16 + i8 + (g & 1) * 8;
                int ch  = ks * 2 + (g >> 1);
                LDM_X4(a[mb], sA + tile_off(row, ch));
            }
#pragma unroll
            for (int np = 0; np < 2; np++) {
                int row = Bnb + np * 16 + i8 + (g >> 1) * 8;
                int ch  = ks * 2 + (g & 1);
                LDM_X4(b[np], sB + tile_off(row, ch));
            }
#pragma unroll
            for (int mb = 0; mb < 4; mb++)
#pragma unroll
                for (int nb = 0; nb < 4; nb++)
                    MMA_S8(acc[mb][nb], a[mb],
                           b[nb >> 1][(nb & 1) * 2], b[nb >> 1][(nb & 1) * 2 + 1]);
        }
    }

    // ---- epilogue: dequant + bias, direct float2 stores ----
#pragma unroll
    for (int mb = 0; mb < 4; mb++) {
        int r0 = m0 + Amb + mb * 16 + (lane >> 2);
        float sx0 = sx[r0], sx1 = sx[r0 + 8];
#pragma unroll
        for (int nb = 0; nb < 4; nb++) {
            int c0 = n0 + Bnb + nb * 8 + (lane & 3) * 2;
            float w0 = ws[c0],  w1 = ws[c0 + 1];
            float f0 = bias[c0], f1 = bias[c0 + 1];
            float2 v0, v1;
            v0.x = (float)acc[mb][nb][0] * sx0 * w0 + f0;
            v0.y = (float)acc[mb][nb][1] * sx0 * w1 + f1;
            v1.x = (float)acc[mb][nb][2] * sx1 * w0 + f0;
            v1.y = (float)acc[mb][nb][3] * sx1 * w1 + f1;
            *(float2*)&out[(size_t)r0 * D_DIM + c0]       = v0;
            *(float2*)&out[(size_t)(r0 + 8) * D_DIM + c0] = v1;
        }
    }
}

// ============================================================================
// Host launcher
// ============================================================================
extern "C" void kernel_launch(void* const* d_in, const int* in_sizes, int n_in,
                              void* d_out, int out_size)
{
    const float* x    = (const float*)d_in[0];
    const int*   wi   = (const int*)  d_in[1];
    const float* wsc  = (const float*)d_in[2];
    const float* bias = (const float*)d_in[3];
    float*       out  = (float*)d_out;

    void *pqx = nullptr, *pwq = nullptr, *psx = nullptr;
    cudaGetSymbolAddress(&pqx, g_qx);
    cudaGetSymbolAddress(&pwq, g_wq);
    cudaGetSymbolAddress(&psx, g_sx);

    // 1) weights int32 -> int8
    int n4 = (D_DIM * D_DIM) / 4;
    wconv_kernel<<<(n4 + 255) / 256, 256>>>((const int4*)wi, (char4*)pwq, n4);

    // 2) Hadamard rotate + quantize activations
    hadq_kernel<<<D_DIM, 512>>>(x, (signed char*)pqx, (float*)psx);

    // 3) GEMM + fused dequant
    static bool attr_set = false;
    if (!attr_set) {
        cudaFuncSetAttribute(gemm_kernel, cudaFuncAttributeMaxDynamicSharedMemorySize,
                             2 * NSTAGE * 8192);
        attr_set = true;
    }
    dim3 grid(D_DIM / BM, D_DIM / BN, 1);
    gemm_kernel<<<grid, THREADS, 2 * NSTAGE * 8192>>>(
        (const signed char*)pqx, (const signed char*)pwq,
        (const float*)psx, wsc, bias, out);
}

// round 3
// speedup vs baseline: 1.4441x; 1.4441x over previous
#include <cuda_runtime.h>
#include <cstdint>

// ============================================================================
// Problem constants
// ============================================================================
#define D_DIM 4096
#define BM 128
#define BN 256
#define BK 64                   // bytes of K per pipeline stage
#define NSTAGE 4
#define KT_ITERS (D_DIM / BK)   // 64
#define THREADS 512

#define A_STAGE 8192            // 128 rows x 64B
#define B_STAGE 16384           // 256 rows x 64B
#define STAGE_BYTES (A_STAGE + B_STAGE)

// ============================================================================
// Scratch (device globals; no allocation allowed)
// ============================================================================
__device__ __align__(1024) signed char g_qx[(size_t)D_DIM * D_DIM]; // int8 activations
__device__ __align__(1024) signed char g_wq[(size_t)D_DIM * D_DIM]; // int8 weights
__device__ float g_sx[D_DIM];                                        // activation row scales

// ============================================================================
// PTX helpers — base ISA only (sm_80+)
// ============================================================================
__device__ __forceinline__ uint32_t smem_u32(const void* p) {
    uint32_t a;
    asm("{ .reg .u64 t; cvta.to.shared.u64 t, %1; cvt.u32.u64 %0, t; }" : "=r"(a) : "l"(p));
    return a;
}

#define CP_ASYNC16(dst, src) \
    asm volatile("cp.async.cg.shared.global [%0], [%1], 16;" :: "r"(dst), "l"(src))
#define CP_COMMIT() asm volatile("cp.async.commit_group;" ::: "memory")
#define CP_WAIT2()  asm volatile("cp.async.wait_group 2;" ::: "memory")

#define LDM_X4(r, addr) \
    asm volatile("ldmatrix.sync.aligned.m8n8.x4.shared.b16 {%0,%1,%2,%3}, [%4];" \
                 : "=r"((r)[0]), "=r"((r)[1]), "=r"((r)[2]), "=r"((r)[3]) : "r"(addr))

#define MMA_S8(c, a, b0, b1) \
    asm volatile("mma.sync.aligned.m16n8k32.row.col.s32.s8.s8.s32 " \
                 "{%0,%1,%2,%3},{%4,%5,%6,%7},{%8,%9},{%0,%1,%2,%3};" \
                 : "+r"((c)[0]), "+r"((c)[1]), "+r"((c)[2]), "+r"((c)[3]) \
                 : "r"((a)[0]), "r"((a)[1]), "r"((a)[2]), "r"((a)[3]), "r"(b0), "r"(b1))

// SMEM tile: rows x 64B, 16B chunks swizzled: phys_chunk = chunk ^ ((row>>1)&3)
__device__ __forceinline__ uint32_t tile_off(int row, int chunk) {
    return (uint32_t)(row * 64 + ((chunk ^ ((row >> 1) & 3)) << 4));
}

// ============================================================================
// Kernel 1 (fused prep):
//   blocks [0,4096):      blockwise-256 Hadamard + per-row int4 quantize
//   blocks [4096,8192):   weight int32 -> int8 conversion
// ============================================================================
__global__ __launch_bounds__(512) void prep_kernel(
    const float* __restrict__ x, const int4* __restrict__ wi,
    signed char* __restrict__ qx, char4* __restrict__ wq, float* __restrict__ sxv)
{
    if (blockIdx.x >= 4096) {
        // ---- weight conversion: 1024 int4 per block, 2 per thread ----
        int base = (blockIdx.x - 4096) * 1024 + threadIdx.x;
#pragma unroll
        for (int r = 0; r < 2; r++) {
            int i = base + r * 512;
            int4 v = wi[i];
            char4 u;
            u.x = (signed char)v.x; u.y = (signed char)v.y;
            u.z = (signed char)v.z; u.w = (signed char)v.w;
            wq[i] = u;
        }
        return;
    }

    // ---- Hadamard + quantize: one row per block, warp w = 256-elem segment ----
    __shared__ float smax[16];
    int row  = blockIdx.x;
    int w    = threadIdx.x >> 5;
    int lane = threadIdx.x & 31;

    const float* xr = x + (size_t)row * D_DIM + w * 256;
    float v[8];
#pragma unroll
    for (int j = 0; j < 8; j++) v[j] = xr[j * 32 + lane];

#pragma unroll
    for (int b = 1; b < 8; b <<= 1) {
#pragma unroll
        for (int j = 0; j < 8; j++) {
            if (!(j & b)) {
                float a = v[j], c = v[j | b];
                v[j] = a + c; v[j | b] = a - c;
            }
        }
    }
#pragma unroll
    for (int s = 1; s < 32; s <<= 1) {
#pragma unroll
        for (int j = 0; j < 8; j++) {
            float o = __shfl_xor_sync(0xFFFFFFFFu, v[j], s);
            v[j] = (lane & s) ? (o - v[j]) : (v[j] + o);
        }
    }
#pragma unroll
    for (int j = 0; j < 8; j++) v[j] *= 0.0625f;

    float mx = 0.0f;
#pragma unroll
    for (int j = 0; j < 8; j++) mx = fmaxf(mx, fabsf(v[j]));
#pragma unroll
    for (int s = 16; s; s >>= 1) mx = fmaxf(mx, __shfl_xor_sync(0xFFFFFFFFu, mx, s));
    if (lane == 0) smax[w] = mx;
    __syncthreads();
    float tot = smax[0];
#pragma unroll
    for (int i = 1; i < 16; i++) tot = fmaxf(tot, smax[i]);

    if (threadIdx.x == 0) sxv[row] = tot * (1.0f / 7.0f);
    float inv = 7.0f / tot;

    signed char* qr = qx + (size_t)row * D_DIM + w * 256;
#pragma unroll
    for (int j = 0; j < 8; j++) {
        float q = rintf(v[j] * inv);
        q = fminf(fmaxf(q, -8.0f), 7.0f);
        qr[j * 32 + lane] = (signed char)(int)q;
    }
}

// ============================================================================
// Kernel 2: int8 GEMM, CTA tile 128x256, 512 threads (16 warps, 4x4),
// warp tile 32x64, 4-stage cp.async pipeline, fused dequant epilogue.
// ============================================================================
__global__ __launch_bounds__(THREADS, 1) void gemm_kernel(
    const signed char* __restrict__ gA,   // [4096,4096] int8 (m,k)
    const signed char* __restrict__ gB,   // [4096,4096] int8 (n,k)
    const float* __restrict__ sx,
    const float* __restrict__ ws,
    const float* __restrict__ bias,
    float* __restrict__ out)
{
    extern __shared__ char smem[];
    uint32_t sbase = smem_u32(smem);
    const uint32_t sA0 = sbase;                     // NSTAGE x A_STAGE
    const uint32_t sB0 = sbase + NSTAGE * A_STAGE;  // NSTAGE x B_STAGE

    int tid  = threadIdx.x;
    int lane = tid & 31;
    int wid  = tid >> 5;
    int m0 = blockIdx.x * BM;
    int n0 = blockIdx.y * BN;
    int wm = wid & 3;           // 4 warps over M
    int wn = wid >> 2;          // 4 warps over N
    int Amb = wm * 32;          // warp M base (32 rows)
    int Bnb = wn * 64;          // warp N base (64 rows)
    int i8 = lane & 7, g = lane >> 3;

    int acc[2][8][4];
#pragma unroll
    for (int a = 0; a < 2; a++)
#pragma unroll
        for (int b = 0; b < 8; b++)
#pragma unroll
            for (int c = 0; c < 4; c++) acc[a][b][c] = 0;

    // per-stage loads: A 512 chunks (1/thread), B 1024 chunks (2/thread)
    int arow = tid >> 2, ach = tid & 3;
    const signed char* gAp = gA + (size_t)(m0 + arow) * D_DIM + ach * 16;
    uint32_t aoff = tile_off(arow, ach);
    int brow0 = tid >> 2,        bch0 = tid & 3;
    int brow1 = (tid + 512) >> 2, bch1 = tid & 3;
    const signed char* gBp0 = gB + (size_t)(n0 + brow0) * D_DIM + bch0 * 16;
    const signed char* gBp1 = gB + (size_t)(n0 + brow1) * D_DIM + bch1 * 16;
    uint32_t boff0 = tile_off(brow0, bch0);
    uint32_t boff1 = tile_off(brow1, bch1);

    auto load_stage = [&](int kt, int buf) {
        int kb = kt * BK;
        uint32_t dA = sA0 + buf * A_STAGE;
        uint32_t dB = sB0 + buf * B_STAGE;
        CP_ASYNC16(dA + aoff,  gAp  + kb);
        CP_ASYNC16(dB + boff0, gBp0 + kb);
        CP_ASYNC16(dB + boff1, gBp1 + kb);
    };

    // precompute ldmatrix smem offsets (stage-relative)
    uint32_t aoffs[2][2], boffs[4][2];   // [tile][ks]
#pragma unroll
    for (int mb = 0; mb < 2; mb++) {
        int row = Amb + mb * 16 + i8 + (g & 1) * 8;
#pragma unroll
        for (int ks = 0; ks < 2; ks++)
            aoffs[mb][ks] = tile_off(row, ks * 2 + (g >> 1));
    }
#pragma unroll
    for (int np = 0; np < 4; np++) {
        int row = Bnb + np * 16 + i8 + (g >> 1) * 8;
#pragma unroll
        for (int ks = 0; ks < 2; ks++)
            boffs[np][ks] = tile_off(row, ks * 2 + (g & 1));
    }

    // prologue: fill 3 stages
#pragma unroll
    for (int s = 0; s < NSTAGE - 1; s++) {
        load_stage(s, s);
        CP_COMMIT();
    }

    for (int kt = 0; kt < KT_ITERS; kt++) {
        CP_WAIT2();
        __syncthreads();

        int ldkt = kt + NSTAGE - 1;
        if (ldkt < KT_ITERS) load_stage(ldkt, ldkt & (NSTAGE - 1));
        CP_COMMIT();

        uint32_t sA = sA0 + (kt & (NSTAGE - 1)) * A_STAGE;
        uint32_t sB = sB0 + (kt & (NSTAGE - 1)) * B_STAGE;

#pragma unroll
        for (int ks = 0; ks < 2; ks++) {
            uint32_t a[2][4], b[4][4];
#pragma unroll
            for (int mb = 0; mb < 2; mb++) LDM_X4(a[mb], sA + aoffs[mb][ks]);
#pragma unroll
            for (int np = 0; np < 4; np++) LDM_X4(b[np], sB + boffs[np][ks]);
#pragma unroll
            for (int mb = 0; mb < 2; mb++)
#pragma unroll
                for (int nb = 0; nb < 8; nb++)
                    MMA_S8(acc[mb][nb], a[mb],
                           b[nb >> 1][(nb & 1) * 2], b[nb >> 1][(nb & 1) * 2 + 1]);
        }
    }

    // ---- epilogue: dequant + bias, direct float2 stores ----
#pragma unroll
    for (int mb = 0; mb < 2; mb++) {
        int r0 = m0 + Amb + mb * 16 + (lane >> 2);
        float sx0 = sx[r0], sx1 = sx[r0 + 8];
#pragma unroll
        for (int nb = 0; nb < 8; nb++) {
            int c0 = n0 + Bnb + nb * 8 + (lane & 3) * 2;
            float w0 = ws[c0],  w1 = ws[c0 + 1];
            float f0 = bias[c0], f1 = bias[c0 + 1];
            float2 v0, v1;
            v0.x = (float)acc[mb][nb][0] * sx0 * w0 + f0;
            v0.y = (float)acc[mb][nb][1] * sx0 * w1 + f1;
            v1.x = (float)acc[mb][nb][2] * sx1 * w0 + f0;
            v1.y = (float)acc[mb][nb][3] * sx1 * w1 + f1;
            *(float2*)&out[(size_t)r0 * D_DIM + c0]       = v0;
            *(float2*)&out[(size_t)(r0 + 8) * D_DIM + c0] = v1;
        }
    }
}

// ============================================================================
// Host launcher
// ============================================================================
extern "C" void kernel_launch(void* const* d_in, const int* in_sizes, int n_in,
                              void* d_out, int out_size)
{
    const float* x    = (const float*)d_in[0];
    const int*   wi   = (const int*)  d_in[1];
    const float* wsc  = (const float*)d_in[2];
    const float* bias = (const float*)d_in[3];
    float*       out  = (float*)d_out;

    void *pqx = nullptr, *pwq = nullptr, *psx = nullptr;
    cudaGetSymbolAddress(&pqx, g_qx);
    cudaGetSymbolAddress(&pwq, g_wq);
    cudaGetSymbolAddress(&psx, g_sx);

    // 1) fused prep: Hadamard+quantize (blocks 0..4095) + weight conv (4096..8191)
    prep_kernel<<<8192, 512>>>(x, (const int4*)wi,
                               (signed char*)pqx, (char4*)pwq, (float*)psx);

    // 2) GEMM + fused dequant
    static bool attr_set = false;
    if (!attr_set) {
        cudaFuncSetAttribute(gemm_kernel, cudaFuncAttributeMaxDynamicSharedMemorySize,
                             NSTAGE * STAGE_BYTES);
        attr_set = true;
    }
    dim3 grid(D_DIM / BM, D_DIM / BN, 1);
    gemm_kernel<<<grid, THREADS, NSTAGE * STAGE_BYTES>>>(
        (const signed char*)pqx, (const signed char*)pwq,
        (const float*)psx, wsc, bias, out);
}

// round 4
// speedup vs baseline: 1.6076x; 1.1132x over previous
#include <cuda_runtime.h>
#include <cstdint>

// ============================================================================
// Problem constants
// ============================================================================
#define D_DIM 4096
#define BM 128
#define BN 128
#define BK 64                   // bytes of K per pipeline stage
#define NSTAGE 4
#define KT_ITERS (D_DIM / BK)   // 64
#define THREADS 256

#define A_STAGE 8192            // 128 rows x 64B
#define B_STAGE 8192
#define STAGE_BYTES (A_STAGE + B_STAGE)

// probe config (fp8 legacy-mma rate test; ~7% of GEMM work)
#define PROBE_GRID 296
#define PROBE_KT   16

// ============================================================================
// Scratch (device globals; no allocation allowed)
// ============================================================================
__device__ __align__(1024) signed char g_qx[(size_t)D_DIM * D_DIM]; // int8 activations
__device__ __align__(1024) signed char g_wq[(size_t)D_DIM * D_DIM]; // int8 weights
__device__ float g_sx[D_DIM];                                        // activation row scales
__device__ float g_probe[65536];                                     // probe sink

// ============================================================================
// PTX helpers — base ISA only
// ============================================================================
__device__ __forceinline__ uint32_t smem_u32(const void* p) {
    uint32_t a;
    asm("{ .reg .u64 t; cvta.to.shared.u64 t, %1; cvt.u32.u64 %0, t; }" : "=r"(a) : "l"(p));
    return a;
}

#define CP_ASYNC16(dst, src) \
    asm volatile("cp.async.cg.shared.global [%0], [%1], 16;" :: "r"(dst), "l"(src))
#define CP_COMMIT() asm volatile("cp.async.commit_group;" ::: "memory")
#define CP_WAIT2()  asm volatile("cp.async.wait_group 2;" ::: "memory")

#define LDM_X4(r, addr) \
    asm volatile("ldmatrix.sync.aligned.m8n8.x4.shared.b16 {%0,%1,%2,%3}, [%4];" \
                 : "=r"((r)[0]), "=r"((r)[1]), "=r"((r)[2]), "=r"((r)[3]) : "r"(addr))

#define MMA_S8(c, a, b0, b1) \
    asm volatile("mma.sync.aligned.m16n8k32.row.col.s32.s8.s8.s32 " \
                 "{%0,%1,%2,%3},{%4,%5,%6,%7},{%8,%9},{%0,%1,%2,%3};" \
                 : "+r"((c)[0]), "+r"((c)[1]), "+r"((c)[2]), "+r"((c)[3]) \
                 : "r"((a)[0]), "r"((a)[1]), "r"((a)[2]), "r"((a)[3]), "r"(b0), "r"(b1))

// fp8 (e4m3) legacy mma, f32 accum — same fragment geometry as s8 k32
#define MMA_E4M3(c, a, b0, b1) \
    asm volatile("mma.sync.aligned.m16n8k32.row.col.f32.e4m3.e4m3.f32 " \
                 "{%0,%1,%2,%3},{%4,%5,%6,%7},{%8,%9},{%0,%1,%2,%3};" \
                 : "+f"((c)[0]), "+f"((c)[1]), "+f"((c)[2]), "+f"((c)[3]) \
                 : "r"((a)[0]), "r"((a)[1]), "r"((a)[2]), "r"((a)[3]), "r"(b0), "r"(b1))

// SMEM tile: rows x 64B, 16B chunks swizzled: phys_chunk = chunk ^ ((row>>1)&3)
__device__ __forceinline__ uint32_t tile_off(int row, int chunk) {
    return (uint32_t)(row * 64 + ((chunk ^ ((row >> 1) & 3)) << 4));
}

// ============================================================================
// Kernel 1 (fused prep): Hadamard+quantize (blocks 0..4095) + wconv (4096..8191)
// ============================================================================
__global__ __launch_bounds__(512) void prep_kernel(
    const float* __restrict__ x, const int4* __restrict__ wi,
    signed char* __restrict__ qx, char4* __restrict__ wq, float* __restrict__ sxv)
{
    if (blockIdx.x >= 4096) {
        int base = (blockIdx.x - 4096) * 1024 + threadIdx.x;
#pragma unroll
        for (int r = 0; r < 2; r++) {
            int i = base + r * 512;
            int4 v = wi[i];
            char4 u;
            u.x = (signed char)v.x; u.y = (signed char)v.y;
            u.z = (signed char)v.z; u.w = (signed char)v.w;
            wq[i] = u;
        }
        return;
    }

    __shared__ float smax[16];
    int row  = blockIdx.x;
    int w    = threadIdx.x >> 5;
    int lane = threadIdx.x & 31;

    const float* xr = x + (size_t)row * D_DIM + w * 256;
    float v[8];
#pragma unroll
    for (int j = 0; j < 8; j++) v[j] = xr[j * 32 + lane];

#pragma unroll
    for (int b = 1; b < 8; b <<= 1) {
#pragma unroll
        for (int j = 0; j < 8; j++) {
            if (!(j & b)) {
                float a = v[j], c = v[j | b];
                v[j] = a + c; v[j | b] = a - c;
            }
        }
    }
#pragma unroll
    for (int s = 1; s < 32; s <<= 1) {
#pragma unroll
        for (int j = 0; j < 8; j++) {
            float o = __shfl_xor_sync(0xFFFFFFFFu, v[j], s);
            v[j] = (lane & s) ? (o - v[j]) : (v[j] + o);
        }
    }
#pragma unroll
    for (int j = 0; j < 8; j++) v[j] *= 0.0625f;

    float mx = 0.0f;
#pragma unroll
    for (int j = 0; j < 8; j++) mx = fmaxf(mx, fabsf(v[j]));
#pragma unroll
    for (int s = 16; s; s >>= 1) mx = fmaxf(mx, __shfl_xor_sync(0xFFFFFFFFu, mx, s));
    if (lane == 0) smax[w] = mx;
    __syncthreads();
    float tot = smax[0];
#pragma unroll
    for (int i = 1; i < 16; i++) tot = fmaxf(tot, smax[i]);

    if (threadIdx.x == 0) sxv[row] = tot * (1.0f / 7.0f);
    float inv = 7.0f / tot;

    signed char* qr = qx + (size_t)row * D_DIM + w * 256;
#pragma unroll
    for (int j = 0; j < 8; j++) {
        float q = rintf(v[j] * inv);
        q = fminf(fmaxf(q, -8.0f), 7.0f);
        qr[j * 32 + lane] = (signed char)(int)q;
    }
}

// ============================================================================
// Kernel 2: int8 GEMM, tile 128x128, 256 threads (8 warps, 2Mx4N, warp 64x32),
// 4-stage cp.async pipeline, 2 CTAs/SM, fused dequant epilogue.
// ============================================================================
__global__ __launch_bounds__(THREADS, 2) void gemm_kernel(
    const signed char* __restrict__ gA,
    const signed char* __restrict__ gB,
    const float* __restrict__ sx,
    const float* __restrict__ ws,
    const float* __restrict__ bias,
    float* __restrict__ out)
{
    extern __shared__ char smem[];
    uint32_t sbase = smem_u32(smem);
    const uint32_t sA0 = sbase;
    const uint32_t sB0 = sbase + NSTAGE * A_STAGE;

    int tid  = threadIdx.x;
    int lane = tid & 31;
    int wid  = tid >> 5;
    int m0 = blockIdx.x * BM;
    int n0 = blockIdx.y * BN;
    int wm = wid & 1;           // 2 warps over M
    int wn = wid >> 1;          // 4 warps over N
    int Amb = wm * 64;
    int Bnb = wn * 32;
    int i8 = lane & 7, g = lane >> 3;

    int acc[4][4][4];
#pragma unroll
    for (int a = 0; a < 4; a++)
#pragma unroll
        for (int b = 0; b < 4; b++)
#pragma unroll
            for (int c = 0; c < 4; c++) acc[a][b][c] = 0;

    // per-stage loads: 512 chunks A (2/thread) + 512 chunks B (2/thread)
    int row0 = tid >> 2, ch0 = tid & 3;
    int row1 = (tid + 256) >> 2;
    const signed char* gA0 = gA + (size_t)(m0 + row0) * D_DIM + ch0 * 16;
    const signed char* gA1 = gA + (size_t)(m0 + row1) * D_DIM + ch0 * 16;
    const signed char* gB0 = gB + (size_t)(n0 + row0) * D_DIM + ch0 * 16;
    const signed char* gB1 = gB + (size_t)(n0 + row1) * D_DIM + ch0 * 16;
    uint32_t off0 = tile_off(row0, ch0);
    uint32_t off1 = tile_off(row1, ch0);

    auto load_stage = [&](int kt, int buf) {
        int kb = kt * BK;
        uint32_t dA = sA0 + buf * A_STAGE;
        uint32_t dB = sB0 + buf * B_STAGE;
        CP_ASYNC16(dA + off0, gA0 + kb);
        CP_ASYNC16(dA + off1, gA1 + kb);
        CP_ASYNC16(dB + off0, gB0 + kb);
        CP_ASYNC16(dB + off1, gB1 + kb);
    };

    // precomputed ldmatrix offsets
    uint32_t aoffs[4][2], boffs[2][2];
#pragma unroll
    for (int mb = 0; mb < 4; mb++) {
        int row = Amb + mb * 16 + i8 + (g & 1) * 8;
#pragma unroll
        for (int ks = 0; ks < 2; ks++)
            aoffs[mb][ks] = tile_off(row, ks * 2 + (g >> 1));
    }
#pragma unroll
    for (int np = 0; np < 2; np++) {
        int row = Bnb + np * 16 + i8 + (g >> 1) * 8;
#pragma unroll
        for (int ks = 0; ks < 2; ks++)
            boffs[np][ks] = tile_off(row, ks * 2 + (g & 1));
    }

#pragma unroll
    for (int s = 0; s < NSTAGE - 1; s++) {
        load_stage(s, s);
        CP_COMMIT();
    }

    for (int kt = 0; kt < KT_ITERS; kt++) {
        CP_WAIT2();
        __syncthreads();

        int ldkt = kt + NSTAGE - 1;
        if (ldkt < KT_ITERS) load_stage(ldkt, ldkt & (NSTAGE - 1));
        CP_COMMIT();

        uint32_t sA = sA0 + (kt & (NSTAGE - 1)) * A_STAGE;
        uint32_t sB = sB0 + (kt & (NSTAGE - 1)) * B_STAGE;

#pragma unroll
        for (int ks = 0; ks < 2; ks++) {
            uint32_t a[4][4], b[2][4];
#pragma unroll
            for (int mb = 0; mb < 4; mb++) LDM_X4(a[mb], sA + aoffs[mb][ks]);
#pragma unroll
            for (int np = 0; np < 2; np++) LDM_X4(b[np], sB + boffs[np][ks]);
#pragma unroll
            for (int mb = 0; mb < 4; mb++)
#pragma unroll
                for (int nb = 0; nb < 4; nb++)
                    MMA_S8(acc[mb][nb], a[mb],
                           b[nb >> 1][(nb & 1) * 2], b[nb >> 1][(nb & 1) * 2 + 1]);
        }
    }

    // ---- epilogue: dequant + bias, float2 stores ----
#pragma unroll
    for (int mb = 0; mb < 4; mb++) {
        int r0 = m0 + Amb + mb * 16 + (lane >> 2);
        float sx0 = sx[r0], sx1 = sx[r0 + 8];
#pragma unroll
        for (int nb = 0; nb < 4; nb++) {
            int c0 = n0 + Bnb + nb * 8 + (lane & 3) * 2;
            float w0 = ws[c0],  w1 = ws[c0 + 1];
            float f0 = bias[c0], f1 = bias[c0 + 1];
            float2 v0, v1;
            v0.x = (float)acc[mb][nb][0] * sx0 * w0 + f0;
            v0.y = (float)acc[mb][nb][1] * sx0 * w1 + f1;
            v1.x = (float)acc[mb][nb][2] * sx1 * w0 + f0;
            v1.y = (float)acc[mb][nb][3] * sx1 * w1 + f1;
            *(float2*)&out[(size_t)r0 * D_DIM + c0]       = v0;
            *(float2*)&out[(size_t)(r0 + 8) * D_DIM + c0] = v1;
        }
    }
}

// ============================================================================
// Kernel 3: fp8 (e4m3) legacy-mma RATE PROBE. Garbage operands (reinterpreted
// int8 buffers), dummy sink output. ~7% of GEMM work; its cost is read from
// the dur residual. Structure mirrors gemm_kernel exactly.
// ============================================================================
__global__ __launch_bounds__(THREADS, 2) void probe_e4m3_kernel(
    const signed char* __restrict__ gA,
    const signed char* __restrict__ gB,
    float* __restrict__ sink)
{
    extern __shared__ char smem[];
    uint32_t sbase = smem_u32(smem);
    const uint32_t sA0 = sbase;
    const uint32_t sB0 = sbase + NSTAGE * A_STAGE;

    int tid  = threadIdx.x;
    int lane = tid & 31;
    int wid  = tid >> 5;
    int m0 = (blockIdx.x & 7) * BM;
    int n0 = ((blockIdx.x >> 3) & 31) * BN;
    int wm = wid & 1, wn = wid >> 1;
    int Amb = wm * 64, Bnb = wn * 32;
    int i8 = lane & 7, g = lane >> 3;

    float acc[4][4][4];
#pragma unroll
    for (int a = 0; a < 4; a++)
#pragma unroll
        for (int b = 0; b < 4; b++)
#pragma unroll
            for (int c = 0; c < 4; c++) acc[a][b][c] = 0.0f;

    int row0 = tid >> 2, ch0 = tid & 3;
    int row1 = (tid + 256) >> 2;
    const signed char* gA0 = gA + (size_t)(m0 + row0) * D_DIM + ch0 * 16;
    const signed char* gA1 = gA + (size_t)(m0 + row1) * D_DIM + ch0 * 16;
    const signed char* gB0 = gB + (size_t)(n0 + row0) * D_DIM + ch0 * 16;
    const signed char* gB1 = gB + (size_t)(n0 + row1) * D_DIM + ch0 * 16;
    uint32_t off0 = tile_off(row0, ch0);
    uint32_t off1 = tile_off(row1, ch0);

    auto load_stage = [&](int kt, int buf) {
        int kb = kt * BK;
        uint32_t dA = sA0 + buf * A_STAGE;
        uint32_t dB = sB0 + buf * B_STAGE;
        CP_ASYNC16(dA + off0, gA0 + kb);
        CP_ASYNC16(dA + off1, gA1 + kb);
        CP_ASYNC16(dB + off0, gB0 + kb);
        CP_ASYNC16(dB + off1, gB1 + kb);
    };

    uint32_t aoffs[4][2], boffs[2][2];
#pragma unroll
    for (int mb = 0; mb < 4; mb++) {
        int row = Amb + mb * 16 + i8 + (g & 1) * 8;
#pragma unroll
        for (int ks = 0; ks < 2; ks++)
            aoffs[mb][ks] = tile_off(row, ks * 2 + (g >> 1));
    }
#pragma unroll
    for (int np = 0; np < 2; np++) {
        int row = Bnb + np * 16 + i8 + (g >> 1) * 8;
#pragma unroll
        for (int ks = 0; ks < 2; ks++)
            boffs[np][ks] = tile_off(row, ks * 2 + (g & 1));
    }

#pragma unroll
    for (int s = 0; s < NSTAGE - 1; s++) {
        load_stage(s, s);
        CP_COMMIT();
    }

    for (int kt = 0; kt < PROBE_KT; kt++) {
        CP_WAIT2();
        __syncthreads();

        int ldkt = kt + NSTAGE - 1;
        if (ldkt < PROBE_KT) load_stage(ldkt, ldkt & (NSTAGE - 1));
        CP_COMMIT();

        uint32_t sA = sA0 + (kt & (NSTAGE - 1)) * A_STAGE;
        uint32_t sB = sB0 + (kt & (NSTAGE - 1)) * B_STAGE;

#pragma unroll
        for (int ks = 0; ks < 2; ks++) {
            uint32_t a[4][4], b[2][4];
#pragma unroll
            for (int mb = 0; mb < 4; mb++) LDM_X4(a[mb], sA + aoffs[mb][ks]);
#pragma unroll
            for (int np = 0; np < 2; np++) LDM_X4(b[np], sB + boffs[np][ks]);
#pragma unroll
            for (int mb = 0; mb < 4; mb++)
#pragma unroll
                for (int nb = 0; nb < 4; nb++)
                    MMA_E4M3(acc[mb][nb], a[mb],
                             b[nb >> 1][(nb & 1) * 2], b[nb >> 1][(nb & 1) * 2 + 1]);
        }
    }

    float s = 0.0f;
#pragma unroll
    for (int a = 0; a < 4; a++)
#pragma unroll
        for (int b = 0; b < 4; b++)
#pragma unroll
            for (int c = 0; c < 4; c++) s += acc[a][b][c];
    sink[(blockIdx.x * THREADS + tid) & 65535] = s;
}

// ============================================================================
// Host launcher
// ============================================================================
extern "C" void kernel_launch(void* const* d_in, const int* in_sizes, int n_in,
                              void* d_out, int out_size)
{
    const float* x    = (const float*)d_in[0];
    const int*   wi   = (const int*)  d_in[1];
    const float* wsc  = (const float*)d_in[2];
    const float* bias = (const float*)d_in[3];
    float*       out  = (float*)d_out;

    void *pqx = nullptr, *pwq = nullptr, *psx = nullptr, *ppr = nullptr;
    cudaGetSymbolAddress(&pqx, g_qx);
    cudaGetSymbolAddress(&pwq, g_wq);
    cudaGetSymbolAddress(&psx, g_sx);
    cudaGetSymbolAddress(&ppr, g_probe);

    static bool attr_set = false;
    if (!attr_set) {
        cudaFuncSetAttribute(gemm_kernel, cudaFuncAttributeMaxDynamicSharedMemorySize,
                             NSTAGE * STAGE_BYTES);
        cudaFuncSetAttribute(probe_e4m3_kernel, cudaFuncAttributeMaxDynamicSharedMemorySize,
                             NSTAGE * STAGE_BYTES);
        attr_set = true;
    }

    // 1) fused prep
    prep_kernel<<<8192, 512>>>(x, (const int4*)wi,
                               (signed char*)pqx, (char4*)pwq, (float*)psx);

    // 2) GEMM + fused dequant
    dim3 grid(D_DIM / BM, D_DIM / BN, 1);
    gemm_kernel<<<grid, THREADS, NSTAGE * STAGE_BYTES>>>(
        (const signed char*)pqx, (const signed char*)pwq,
        (const float*)psx, wsc, bias, out);

    // 3) fp8 legacy-mma rate probe (cost = dur residual)
    probe_e4m3_kernel<<<PROBE_GRID, THREADS, NSTAGE * STAGE_BYTES>>>(
        (const signed char*)pqx, (const signed char*)pwq, (float*)ppr);
}